// round 6
// baseline (speedup 1.0000x reference)
#include <cuda_runtime.h>
#include <cuda_fp16.h>
#include <cstdint>
#include <cstddef>

// ---------------------------------------------------------------------------
// Problem constants
// ---------------------------------------------------------------------------
static constexpr int NSTK  = 65536;
static constexpr int NFEAT = 768;
static constexpr int NH    = 512;
static constexpr int NACT  = 3;

// GEMM1 tiling: CTA 128(M) x 128(N) x 32(K), 256 threads, 4-stage cp.async
static constexpr int BLKM = 128;
static constexpr int BLKN = 128;
static constexpr int BLKK = 32;
static constexpr int NKCH = NFEAT / BLKK;     // 24 K-chunks
static constexpr int STAGES = 4;
// per stage: Ahi 8K, Alo 8K, Bhi 8K, Blo 8K = 32KB
static constexpr int STAGE_BYTES = 4 * BLKM * BLKK * 2;  // 32768
static constexpr int SMEM_DYN = STAGES * STAGE_BYTES;     // 131072

// ---------------------------------------------------------------------------
// Device scratch (static globals: allocation-free)
// ---------------------------------------------------------------------------
__device__ __half g_xhi[(size_t)NSTK * NFEAT];
__device__ __half g_xlo[(size_t)NSTK * NFEAT];
__device__ __half g_whh[NH * NFEAT];
__device__ __half g_whl[NH * NFEAT];
__device__ float  g_h[(size_t)NSTK * NH];
__device__ float  g_hpart[512 * 512];     // [m_tile][col] partial column sums
__device__ float  g_weff[NACT * NH];
__device__ float  g_cterm[NACT];

// ---------------------------------------------------------------------------
// PTX helpers (arch-agnostic: sm_80-level features only)
// ---------------------------------------------------------------------------
__device__ __forceinline__ uint32_t smem_u32(const void* p) {
    uint32_t a;
    asm("{ .reg .u64 t; cvta.to.shared.u64 t, %1; cvt.u32.u64 %0, t; }" : "=r"(a) : "l"(p));
    return a;
}
__device__ __forceinline__ void cpa16(uint32_t dst, const void* src) {
    asm volatile("cp.async.cg.shared.global [%0], [%1], 16;" :: "r"(dst), "l"(src));
}
__device__ __forceinline__ void cpa_commit() { asm volatile("cp.async.commit_group;"); }
template <int N> __device__ __forceinline__ void cpa_wait() {
    asm volatile("cp.async.wait_group %0;" :: "n"(N));
}
#define LDMX4(r, addr)                                                          \
    asm volatile("ldmatrix.sync.aligned.m8n8.x4.shared.b16 {%0,%1,%2,%3}, [%4];" \
        : "=r"((r)[0]), "=r"((r)[1]), "=r"((r)[2]), "=r"((r)[3]) : "r"(addr))

__device__ __forceinline__ void mma16816(float* d, const uint32_t* a, const uint32_t* b) {
    asm volatile(
        "mma.sync.aligned.m16n8k16.row.col.f32.f16.f16.f32 "
        "{%0,%1,%2,%3}, {%4,%5,%6,%7}, {%8,%9}, {%0,%1,%2,%3};"
        : "+f"(d[0]), "+f"(d[1]), "+f"(d[2]), "+f"(d[3])
        : "r"(a[0]), "r"(a[1]), "r"(a[2]), "r"(a[3]), "r"(b[0]), "r"(b[1]));
}

// smem swizzle: row stride 64B (4 x 16B granules); granule ^= (row>>1)&3
__device__ __forceinline__ uint32_t soff(int row, int g) {
    return (uint32_t)(row * 64 + (((g) ^ ((row >> 1) & 3)) << 4));
}

// ---------------------------------------------------------------------------
// Kernel 1: split-convert x and Wh (f32 -> fp16 hi + fp16 lo residual)
// ---------------------------------------------------------------------------
__global__ void k_convert(const float* __restrict__ x, const float* __restrict__ wh) {
    const int NX4 = NSTK * NFEAT / 4;
    const int NW4 = NH * NFEAT / 4;
    const int total = NX4 + NW4;
    for (int i = blockIdx.x * blockDim.x + threadIdx.x; i < total;
         i += gridDim.x * blockDim.x) {
        const float4* src;
        __half2 *hip, *lop;
        int j;
        if (i < NX4) {
            src = (const float4*)x;
            hip = (__half2*)g_xhi; lop = (__half2*)g_xlo; j = i;
        } else {
            src = (const float4*)wh;
            hip = (__half2*)g_whh; lop = (__half2*)g_whl; j = i - NX4;
        }
        float4 v = src[j];
        __half hx = __float2half(v.x), hy = __float2half(v.y);
        __half hz = __float2half(v.z), hw = __float2half(v.w);
        __half lx = __float2half(v.x - __half2float(hx));
        __half ly = __float2half(v.y - __half2float(hy));
        __half lz = __float2half(v.z - __half2float(hz));
        __half lw = __float2half(v.w - __half2float(hw));
        hip[2 * j]     = __halves2half2(hx, hy);
        hip[2 * j + 1] = __halves2half2(hz, hw);
        lop[2 * j]     = __halves2half2(lx, ly);
        lop[2 * j + 1] = __halves2half2(lz, lw);
    }
}

// ---------------------------------------------------------------------------
// Kernel 2: GEMM1 h = relu(x @ Wh^T + bh) with split-fp16 (3 mma pairs),
// mma.sync m16n8k16 + ldmatrix + cp.async 4-stage pipeline.
// grid (4, 512): blockIdx.x = n_tile, blockIdx.y = m_tile. 256 threads.
// Also emits deterministic per-CTA column sums into g_hpart.
// ---------------------------------------------------------------------------
__global__ void __launch_bounds__(256, 1) k_gemm1(const float* __restrict__ bh) {
    extern __shared__ char smem[];
    __shared__ float sred[8][64];
    __shared__ float sbh[128];
    const uint32_t sb = smem_u32(smem);

    const int tid = threadIdx.x, wid = tid >> 5, lid = tid & 31;
    const int ntile = blockIdx.x, mtile = blockIdx.y;

    if (tid < 128) sbh[tid] = bh[ntile * 128 + tid];

    // global tile bases (byte pointers); chunk k adds k*64 bytes
    const char* pAh = (const char*)g_xhi + (size_t)mtile * 128 * 1536;
    const char* pAl = (const char*)g_xlo + (size_t)mtile * 128 * 1536;
    const char* pBh = (const char*)g_whh + (size_t)ntile * 128 * 1536;
    const char* pBl = (const char*)g_whl + (size_t)ntile * 128 * 1536;

    auto load_chunk = [&](int k, int s) {
        const uint32_t st = sb + s * STAGE_BYTES;
        const size_t kb = (size_t)k * 64;
#pragma unroll
        for (int it = 0; it < 2; ++it) {
            int idx = tid + it * 256;           // 512 granules: 128 rows x 4
            int r = idx >> 2, g = idx & 3;
            uint32_t so = soff(r, g);
            size_t go = (size_t)r * 1536 + (size_t)g * 16 + kb;
            cpa16(st + so,          pAh + go);
            cpa16(st + 8192 + so,   pAl + go);
            cpa16(st + 16384 + so,  pBh + go);
            cpa16(st + 24576 + so,  pBl + go);
        }
        cpa_commit();
    };

    load_chunk(0, 0);
    load_chunk(1, 1);
    load_chunk(2, 2);

    float acc[2][8][4];
#pragma unroll
    for (int mi = 0; mi < 2; ++mi)
#pragma unroll
        for (int ni = 0; ni < 8; ++ni)
#pragma unroll
            for (int e = 0; e < 4; ++e) acc[mi][ni][e] = 0.0f;

    const int mw = (wid >> 1) * 32;     // warp M offset (0,32,64,96)
    const int nw = (wid & 1) * 64;      // warp N offset (0,64)
    const int rloc = lid & 15, c0 = lid >> 4;
    const uint32_t aoff0 = soff(mw + rloc, c0);   // j=0 base, hi buffer
    const uint32_t boff0 = soff(nw + rloc, c0);

    for (int k = 0; k < NKCH; ++k) {
        cpa_wait<2>();
        __syncthreads();
        if (k + 3 < NKCH) load_chunk(k + 3, (k + 3) & 3);
        else cpa_commit();   // keep group count uniform for wait<2>

        const uint32_t st = sb + (k & 3) * STAGE_BYTES;
#pragma unroll
        for (int j = 0; j < 2; ++j) {
            const uint32_t jx = j ? 32u : 0u;   // granule +2 == XOR 32 on swizzled addr
            uint32_t ah[2][4], al[2][4], bhf[8][2], blf[8][2];
#pragma unroll
            for (int mi = 0; mi < 2; ++mi) {
                LDMX4(ah[mi], st + ((aoff0 + mi * 1024) ^ jx));
                LDMX4(al[mi], st + 8192 + ((aoff0 + mi * 1024) ^ jx));
            }
#pragma unroll
            for (int nq = 0; nq < 4; ++nq) {
                uint32_t t[4];
                LDMX4(t, st + 16384 + ((boff0 + nq * 1024) ^ jx));
                bhf[2 * nq][0] = t[0]; bhf[2 * nq][1] = t[2];
                bhf[2 * nq + 1][0] = t[1]; bhf[2 * nq + 1][1] = t[3];
                LDMX4(t, st + 24576 + ((boff0 + nq * 1024) ^ jx));
                blf[2 * nq][0] = t[0]; blf[2 * nq][1] = t[2];
                blf[2 * nq + 1][0] = t[1]; blf[2 * nq + 1][1] = t[3];
            }
            // pair 0: Ahi*Bhi, pair 1: Alo*Bhi, pair 2: Ahi*Blo
#pragma unroll
            for (int mi = 0; mi < 2; ++mi)
#pragma unroll
                for (int ni = 0; ni < 8; ++ni) mma16816(acc[mi][ni], ah[mi], bhf[ni]);
#pragma unroll
            for (int mi = 0; mi < 2; ++mi)
#pragma unroll
                for (int ni = 0; ni < 8; ++ni) mma16816(acc[mi][ni], al[mi], bhf[ni]);
#pragma unroll
            for (int mi = 0; mi < 2; ++mi)
#pragma unroll
                for (int ni = 0; ni < 8; ++ni) mma16816(acc[mi][ni], ah[mi], blf[ni]);
        }
    }
    __syncthreads();

    // ---- Epilogue: bias + relu, store h, deterministic column sums ----
    const int rbase = mtile * 128 + mw + (lid >> 2);
    const int q2 = (lid & 3) * 2;
#pragma unroll
    for (int mi = 0; mi < 2; ++mi) {
#pragma unroll
        for (int ni = 0; ni < 8; ++ni) {
            const int cl = nw + ni * 8 + q2;                // local col 0..127
            const float b0 = sbh[cl], b1 = sbh[cl + 1];
            float v0 = fmaxf(acc[mi][ni][0] + b0, 0.0f);
            float v1 = fmaxf(acc[mi][ni][1] + b1, 0.0f);
            float v2 = fmaxf(acc[mi][ni][2] + b0, 0.0f);
            float v3 = fmaxf(acc[mi][ni][3] + b1, 0.0f);
            acc[mi][ni][0] = v0; acc[mi][ni][1] = v1;
            acc[mi][ni][2] = v2; acc[mi][ni][3] = v3;
            const size_t r0 = (size_t)(rbase + mi * 16) * NH + ntile * 128 + cl;
            const size_t r1 = r0 + (size_t)8 * NH;
            *(float2*)(g_h + r0) = make_float2(v0, v1);
            *(float2*)(g_h + r1) = make_float2(v2, v3);
        }
    }
    // column sums over this CTA's 128 rows (order fixed: warp-local, then warp 0..3)
#pragma unroll
    for (int ni = 0; ni < 8; ++ni) {
        float p0 = acc[0][ni][0] + acc[0][ni][2] + acc[1][ni][0] + acc[1][ni][2];
        float p1 = acc[0][ni][1] + acc[0][ni][3] + acc[1][ni][1] + acc[1][ni][3];
#pragma unroll
        for (int off = 4; off < 32; off <<= 1) {
            p0 += __shfl_xor_sync(0xffffffffu, p0, off);
            p1 += __shfl_xor_sync(0xffffffffu, p1, off);
        }
        if (lid < 4) {
            sred[wid][ni * 8 + 2 * lid]     = p0;
            sred[wid][ni * 8 + 2 * lid + 1] = p1;
        }
    }
    __syncthreads();
    if (tid < 128) {
        const int half = tid >> 6, cl = tid & 63;
        float cs = sred[half][cl] + sred[half + 2][cl] + sred[half + 4][cl] + sred[half + 6][cl];
        g_hpart[mtile * 512 + ntile * 128 + tid] = cs;
    }
}

// ---------------------------------------------------------------------------
// Kernel 3: colsum S (fixed order), Wf_eff, c terms. <<<1, 512>>>
// ---------------------------------------------------------------------------
__global__ void k_pre(const float* __restrict__ Wf, const float* __restrict__ bf) {
    __shared__ float sS[512];
    const int g = threadIdx.x;
    float s = 0.0f;
    for (int m = 0; m < 512; ++m) s += g_hpart[m * 512 + g];
    sS[g] = s;
    const float inv = 1.0f / (float)(NSTK - 1);
#pragma unroll
    for (int a = 0; a < NACT; ++a)
        g_weff[a * NH + g] = Wf[a * (2 * NH) + g] - Wf[a * (2 * NH) + NH + g] * inv;
    __syncthreads();
    if (g < 32) {
#pragma unroll
        for (int a = 0; a < NACT; ++a) {
            float p = 0.0f;
            for (int q = g; q < NH; q += 32) p += sS[q] * Wf[a * (2 * NH) + NH + q];
#pragma unroll
            for (int off = 16; off > 0; off >>= 1)
                p += __shfl_xor_sync(0xffffffffu, p, off);
            if (g == 0) g_cterm[a] = p * inv + bf[a];
        }
    }
}

// ---------------------------------------------------------------------------
// Kernel 4: out[i,a] = relu( h_i . Wf_eff[a] + c[a] ). One warp per row.
// ---------------------------------------------------------------------------
__global__ void __launch_bounds__(256) k_out(float* __restrict__ out) {
    __shared__ float swe[NACT * NH];
    __shared__ float sc[NACT];
    const int tid = threadIdx.x;
    for (int i = tid; i < NACT * NH; i += 256) swe[i] = g_weff[i];
    if (tid < NACT) sc[tid] = g_cterm[tid];
    __syncthreads();
    const int wid = tid >> 5, lid = tid & 31;
    const size_t row = (size_t)blockIdx.x * 8 + wid;
    const float4* h4  = (const float4*)(g_h + row * NH);
    const float4* we4 = (const float4*)swe;
    float a0 = 0.f, a1 = 0.f, a2 = 0.f;
#pragma unroll
    for (int i = 0; i < 4; ++i) {
        float4 hv = h4[lid + 32 * i];
        float4 w0 = we4[lid + 32 * i];
        float4 w1 = we4[128 + lid + 32 * i];
        float4 w2 = we4[256 + lid + 32 * i];
        a0 += hv.x * w0.x + hv.y * w0.y + hv.z * w0.z + hv.w * w0.w;
        a1 += hv.x * w1.x + hv.y * w1.y + hv.z * w1.z + hv.w * w1.w;
        a2 += hv.x * w2.x + hv.y * w2.y + hv.z * w2.z + hv.w * w2.w;
    }
#pragma unroll
    for (int off = 16; off > 0; off >>= 1) {
        a0 += __shfl_xor_sync(0xffffffffu, a0, off);
        a1 += __shfl_xor_sync(0xffffffffu, a1, off);
        a2 += __shfl_xor_sync(0xffffffffu, a2, off);
    }
    if (lid == 0) {
        out[row * 3 + 0] = fmaxf(a0 + sc[0], 0.0f);
        out[row * 3 + 1] = fmaxf(a1 + sc[1], 0.0f);
        out[row * 3 + 2] = fmaxf(a2 + sc[2], 0.0f);
    }
}

// ---------------------------------------------------------------------------
// Host launcher
// ---------------------------------------------------------------------------
extern "C" void kernel_launch(void* const* d_in, const int* in_sizes, int n_in,
                              void* d_out, int out_size) {
    const float *x = nullptr, *Wh = nullptr, *bh = nullptr, *Wf = nullptr, *bf = nullptr;
    for (int i = 0; i < n_in; ++i) {
        switch (in_sizes[i]) {
            case NSTK * NFEAT:  x  = (const float*)d_in[i]; break;  // 50331648
            case NH * NFEAT:    Wh = (const float*)d_in[i]; break;  // 393216
            case NH:            bh = (const float*)d_in[i]; break;  // 512
            case NACT * 2 * NH: Wf = (const float*)d_in[i]; break;  // 3072
            case NACT:          bf = (const float*)d_in[i]; break;  // 3
            default: break;
        }
    }
    float* out = (float*)d_out;

    static bool attr_set = false;
    if (!attr_set) {
        cudaFuncSetAttribute(k_gemm1, cudaFuncAttributeMaxDynamicSharedMemorySize, SMEM_DYN);
        attr_set = true;
    }

    k_convert<<<8192, 256>>>(x, Wh);
    k_gemm1<<<dim3(4, 512), 256, SMEM_DYN>>>(bh);
    k_pre<<<1, 512>>>(Wf, bf);
    k_out<<<NSTK / 8, 256>>>(out);
}

// round 9
// speedup vs baseline: 1.1673x; 1.1673x over previous
#include <cuda_runtime.h>
#include <cuda_fp16.h>
#include <cstdint>
#include <cstddef>

// ---------------------------------------------------------------------------
// Problem constants
// ---------------------------------------------------------------------------
static constexpr int NSTK  = 65536;
static constexpr int NFEAT = 768;
static constexpr int NH    = 512;
static constexpr int NACT  = 3;

// GEMM tiling: CTA 128(M) x 256(N) x 32(K), 256 threads, warp tile 64x64.
// 3-stage cp.async pipeline. x loaded as fp32 and split to fp16 hi/lo in smem.
static constexpr int NKCH = NFEAT / 32;          // 24 K-chunks
// stage: A32 (128x32 f32 = 16KB) + Bhi (256x32 f16 = 16KB) + Blo (16KB)
static constexpr int ST_A32 = 0;
static constexpr int ST_BH  = 16384;
static constexpr int ST_BL  = 32768;
static constexpr int STAGE_BYTES = 49152;
static constexpr int STAGES = 3;
static constexpr int A16H_OFF = STAGES * STAGE_BYTES;          // 147456 (8KB)
static constexpr int A16L_OFF = A16H_OFF + 8192;               // 155648 (8KB)
static constexpr int SMEM_DYN = A16L_OFF + 8192;               // 163840

// ---------------------------------------------------------------------------
// Device scratch (static globals: allocation-free)
// ---------------------------------------------------------------------------
__device__ __half g_whh[NH * NFEAT];
__device__ __half g_whl[NH * NFEAT];
__device__ float  g_hpart[512 * 512];              // [m_tile][col] colsum parts
__device__ float  g_dotp[(size_t)NSTK * 12];       // per-row 6 dots x 2 ntiles
__device__ float  g_cterm[NACT];

// ---------------------------------------------------------------------------
// PTX helpers (arch-agnostic, sm_80-level)
// ---------------------------------------------------------------------------
__device__ __forceinline__ uint32_t smem_u32(const void* p) {
    uint32_t a;
    asm("{ .reg .u64 t; cvta.to.shared.u64 t, %1; cvt.u32.u64 %0, t; }" : "=r"(a) : "l"(p));
    return a;
}
__device__ __forceinline__ void cpa16(uint32_t dst, const void* src) {
    asm volatile("cp.async.cg.shared.global [%0], [%1], 16;" :: "r"(dst), "l"(src));
}
__device__ __forceinline__ void cpa_commit() { asm volatile("cp.async.commit_group;"); }
template <int N> __device__ __forceinline__ void cpa_wait() {
    asm volatile("cp.async.wait_group %0;" :: "n"(N));
}
#define LDMX4(r, addr)                                                          \
    asm volatile("ldmatrix.sync.aligned.m8n8.x4.shared.b16 {%0,%1,%2,%3}, [%4];" \
        : "=r"((r)[0]), "=r"((r)[1]), "=r"((r)[2]), "=r"((r)[3]) : "r"(addr))

__device__ __forceinline__ void mma16816(float* d, const uint32_t* a, const uint32_t* b) {
    asm volatile(
        "mma.sync.aligned.m16n8k16.row.col.f32.f16.f16.f32 "
        "{%0,%1,%2,%3}, {%4,%5,%6,%7}, {%8,%9}, {%0,%1,%2,%3};"
        : "+f"(d[0]), "+f"(d[1]), "+f"(d[2]), "+f"(d[3])
        : "r"(a[0]), "r"(a[1]), "r"(a[2]), "r"(a[3]), "r"(b[0]), "r"(b[1]));
}
// 64B-row swizzle for f16 tiles: granule ^= (row>>1)&3
__device__ __forceinline__ uint32_t soff(int row, int g) {
    return (uint32_t)(row * 64 + ((g ^ ((row >> 1) & 3)) << 4));
}

// ---------------------------------------------------------------------------
// Kernel 0: split W into fp16 hi + lo (tiny)
// ---------------------------------------------------------------------------
__global__ void k_wsplit(const float* __restrict__ wh) {
    int i = blockIdx.x * blockDim.x + threadIdx.x;   // 98304 float4 tasks
    float4 v = ((const float4*)wh)[i];
    __half hx = __float2half_rn(v.x), hy = __float2half_rn(v.y);
    __half hz = __float2half_rn(v.z), hw = __float2half_rn(v.w);
    __half lx = __float2half_rn(v.x - __half2float(hx));
    __half ly = __float2half_rn(v.y - __half2float(hy));
    __half lz = __float2half_rn(v.z - __half2float(hz));
    __half lw = __float2half_rn(v.w - __half2float(hw));
    ((__half2*)g_whh)[2 * i]     = __halves2half2(hx, hy);
    ((__half2*)g_whh)[2 * i + 1] = __halves2half2(hz, hw);
    ((__half2*)g_whl)[2 * i]     = __halves2half2(lx, ly);
    ((__half2*)g_whl)[2 * i + 1] = __halves2half2(lz, lw);
}

// ---------------------------------------------------------------------------
// Kernel 1: fused GEMM1 + epilogue.
//   h = relu(x @ Wh^T + bh) (3-term split-fp16, never stored)
//   emits: per-CTA column sums -> g_hpart, per-row layer2 dots -> g_dotp
// grid (2, 512): blockIdx.x = ntile (256 N-cols), blockIdx.y = mtile (128 rows)
// ---------------------------------------------------------------------------
__global__ void __launch_bounds__(256, 1) k_gemm1(const float* __restrict__ bh,
                                                  const float* __restrict__ Wf) {
    extern __shared__ char smem[];
    __shared__ float sbh[256];
    __shared__ float sWf1[3][256];
    __shared__ float sWf2[3][256];
    __shared__ float sred[8][64];
    __shared__ float sdot[4][128][6];
    const uint32_t sb = smem_u32(smem);

    const int tid = threadIdx.x, wid = tid >> 5, lid = tid & 31;
    const int ntile = blockIdx.x, mtile = blockIdx.y;

    sbh[tid] = bh[ntile * 256 + tid];
#pragma unroll
    for (int a = 0; a < 3; ++a) {
        sWf1[a][tid] = Wf[a * 1024 + ntile * 256 + tid];
        sWf2[a][tid] = Wf[a * 1024 + 512 + ntile * 256 + tid];
    }

    // x as fp32 (bytes); W hi/lo halves (bytes)
    extern __shared__ char sm2[];
    const char* px  = (const char*)0;  // set below via param trick
    (void)px;
    const float* xbase = nullptr;      // placeholder; x passed via g? -> use param
    (void)xbase;
    // NOTE: x pointer delivered through bh? No — pass via additional param below.
    // (actual x pointer is the third kernel parameter)
    // -- see k_gemm1_real below --
    // This stub never used.
    sdot[0][0][0] = 0.0f;
}

// Real GEMM kernel (separate to keep x as a parameter cleanly)
__global__ void __launch_bounds__(256, 1) k_gemm(const float* __restrict__ x,
                                                 const float* __restrict__ bh,
                                                 const float* __restrict__ Wf) {
    extern __shared__ char smem[];
    __shared__ float sbh[256];
    __shared__ float sWf1[3][256];
    __shared__ float sWf2[3][256];
    __shared__ float sred[8][64];
    __shared__ float sdot[4][128][6];
    const uint32_t sb = smem_u32(smem);

    const int tid = threadIdx.x, wid = tid >> 5, lid = tid & 31;
    const int ntile = blockIdx.x, mtile = blockIdx.y;

    sbh[tid] = bh[ntile * 256 + tid];
#pragma unroll
    for (int a = 0; a < 3; ++a) {
        sWf1[a][tid] = Wf[a * 1024 + ntile * 256 + tid];
        sWf2[a][tid] = Wf[a * 1024 + 512 + ntile * 256 + tid];
    }

    const char* pX  = (const char*)x + (size_t)mtile * 128 * 3072;   // f32 rows, 3072B
    const char* pBh = (const char*)g_whh + (size_t)ntile * 256 * 1536;
    const char* pBl = (const char*)g_whl + (size_t)ntile * 256 * 1536;

    auto load_chunk = [&](int k, int s) {
        const uint32_t st = sb + s * STAGE_BYTES;
        // A32: 128 rows x 8 granules (linear 128B rows)
#pragma unroll
        for (int it = 0; it < 4; ++it) {
            int idx = tid + it * 256;
            int r = idx >> 3, g = idx & 7;
            cpa16(st + ST_A32 + r * 128 + g * 16,
                  pX + (size_t)r * 3072 + (size_t)k * 128 + g * 16);
        }
        // B hi/lo: 256 rows x 4 granules, swizzled 64B rows
#pragma unroll
        for (int it = 0; it < 4; ++it) {
            int idx = tid + it * 256;
            int r = idx >> 2, g = idx & 3;
            uint32_t so = soff(r, g);
            size_t go = (size_t)r * 1536 + (size_t)g * 16 + (size_t)k * 64;
            cpa16(st + ST_BH + so, pBh + go);
            cpa16(st + ST_BL + so, pBl + go);
        }
        cpa_commit();
    };

    load_chunk(0, 0);
    load_chunk(1, 1);

    float acc[4][8][4];
#pragma unroll
    for (int mi = 0; mi < 4; ++mi)
#pragma unroll
        for (int ni = 0; ni < 8; ++ni)
#pragma unroll
            for (int e = 0; e < 4; ++e) acc[mi][ni][e] = 0.0f;

    const int wm = (wid & 1) * 64;        // warp M offset (0, 64)
    const int wn = (wid >> 1) * 64;       // warp N offset (0, 64, 128, 192)
    const int rloc = lid & 15, c0 = lid >> 4;
    const uint32_t aoff0 = soff(wm + rloc, c0);
    const uint32_t boff0 = soff(wn + rloc, c0);

    for (int k = 0; k < NKCH; ++k) {
        cpa_wait<1>();
        __syncthreads();
        if (k + 2 < NKCH) load_chunk(k + 2, (k + 2) % 3);
        else cpa_commit();

        const uint32_t st = sb + (k % 3) * STAGE_BYTES;

        // ---- convert A32 -> A16 hi/lo (512 tasks of 8 floats) ----
#pragma unroll
        for (int it = 0; it < 2; ++it) {
            int t = tid + it * 256;
            int r = t >> 2, gh = t & 3;
            const float4* src = (const float4*)(smem + (k % 3) * STAGE_BYTES
                                                + ST_A32 + r * 128 + gh * 32);
            float4 f0 = src[0], f1 = src[1];
            __half h0 = __float2half_rn(f0.x), h1 = __float2half_rn(f0.y);
            __half h2 = __float2half_rn(f0.z), h3 = __float2half_rn(f0.w);
            __half h4 = __float2half_rn(f1.x), h5 = __float2half_rn(f1.y);
            __half h6 = __float2half_rn(f1.z), h7 = __float2half_rn(f1.w);
            __half l0 = __float2half_rn(f0.x - __half2float(h0));
            __half l1 = __float2half_rn(f0.y - __half2float(h1));
            __half l2 = __float2half_rn(f0.z - __half2float(h2));
            __half l3 = __float2half_rn(f0.w - __half2float(h3));
            __half l4 = __float2half_rn(f1.x - __half2float(h4));
            __half l5 = __float2half_rn(f1.y - __half2float(h5));
            __half l6 = __float2half_rn(f1.z - __half2float(h6));
            __half l7 = __float2half_rn(f1.w - __half2float(h7));
            uint32_t so = soff(r, gh);
            union { __half2 h2v[4]; uint4 u; } th, tl;
            th.h2v[0] = __halves2half2(h0, h1); th.h2v[1] = __halves2half2(h2, h3);
            th.h2v[2] = __halves2half2(h4, h5); th.h2v[3] = __halves2half2(h6, h7);
            tl.h2v[0] = __halves2half2(l0, l1); tl.h2v[1] = __halves2half2(l2, l3);
            tl.h2v[2] = __halves2half2(l4, l5); tl.h2v[3] = __halves2half2(l6, l7);
            *(uint4*)(smem + A16H_OFF + so) = th.u;
            *(uint4*)(smem + A16L_OFF + so) = tl.u;
        }
        __syncthreads();

        // ---- MMA: 2 K-halves, 3 term-sets, B processed in two 32-col halves --
#pragma unroll
        for (int j = 0; j < 2; ++j) {
            const uint32_t jx = j ? 32u : 0u;
            uint32_t ah[4][4], al[4][4];
#pragma unroll
            for (int mi = 0; mi < 4; ++mi) {
                LDMX4(ah[mi], sb + A16H_OFF + ((aoff0 + mi * 1024) ^ jx));
                LDMX4(al[mi], sb + A16L_OFF + ((aoff0 + mi * 1024) ^ jx));
            }
#pragma unroll
            for (int half = 0; half < 2; ++half) {
                uint32_t bhf[4][2], blf[4][2];
#pragma unroll
                for (int nq = 0; nq < 2; ++nq) {
                    uint32_t t[4];
                    const uint32_t bo = (boff0 + (half * 2 + nq) * 1024) ^ jx;
                    LDMX4(t, st + ST_BH + bo);
                    bhf[2 * nq][0] = t[0]; bhf[2 * nq][1] = t[2];
                    bhf[2 * nq + 1][0] = t[1]; bhf[2 * nq + 1][1] = t[3];
                    LDMX4(t, st + ST_BL + bo);
                    blf[2 * nq][0] = t[0]; blf[2 * nq][1] = t[2];
                    blf[2 * nq + 1][0] = t[1]; blf[2 * nq + 1][1] = t[3];
                }
                const int nb = half * 4;
#pragma unroll
                for (int mi = 0; mi < 4; ++mi)
#pragma unroll
                    for (int ni = 0; ni < 4; ++ni) mma16816(acc[mi][nb + ni], ah[mi], bhf[ni]);
#pragma unroll
                for (int mi = 0; mi < 4; ++mi)
#pragma unroll
                    for (int ni = 0; ni < 4; ++ni) mma16816(acc[mi][nb + ni], al[mi], bhf[ni]);
#pragma unroll
                for (int mi = 0; mi < 4; ++mi)
#pragma unroll
                    for (int ni = 0; ni < 4; ++ni) mma16816(acc[mi][nb + ni], ah[mi], blf[ni]);
            }
        }
    }
    __syncthreads();

    // ---- Epilogue: bias + relu (in regs), colsums, layer-2 dot partials ----
    const int q2 = (lid & 3) * 2;
#pragma unroll
    for (int mi = 0; mi < 4; ++mi)
#pragma unroll
        for (int ni = 0; ni < 8; ++ni) {
            const int cl = wn + ni * 8 + q2;
            const float b0 = sbh[cl], b1 = sbh[cl + 1];
            acc[mi][ni][0] = fmaxf(acc[mi][ni][0] + b0, 0.0f);
            acc[mi][ni][1] = fmaxf(acc[mi][ni][1] + b1, 0.0f);
            acc[mi][ni][2] = fmaxf(acc[mi][ni][2] + b0, 0.0f);
            acc[mi][ni][3] = fmaxf(acc[mi][ni][3] + b1, 0.0f);
        }

    // column sums over this warp's 64 rows (fixed order), 2 cols per lane group
#pragma unroll
    for (int ni = 0; ni < 8; ++ni) {
        float p0 = 0.0f, p1 = 0.0f;
#pragma unroll
        for (int mi = 0; mi < 4; ++mi) {
            p0 += acc[mi][ni][0] + acc[mi][ni][2];
            p1 += acc[mi][ni][1] + acc[mi][ni][3];
        }
#pragma unroll
        for (int off = 4; off < 32; off <<= 1) {
            p0 += __shfl_xor_sync(0xffffffffu, p0, off);
            p1 += __shfl_xor_sync(0xffffffffu, p1, off);
        }
        if (lid < 4) {
            sred[wid][ni * 8 + 2 * lid]     = p0;
            sred[wid][ni * 8 + 2 * lid + 1] = p1;
        }
    }

    // per-row dot partials with Wf1/Wf2 (6 values per row), per mi block
    const int wng = wid >> 1;
#pragma unroll
    for (int mi = 0; mi < 4; ++mi) {
        float dA[6] = {0, 0, 0, 0, 0, 0}, dB[6] = {0, 0, 0, 0, 0, 0};
#pragma unroll
        for (int ni = 0; ni < 8; ++ni) {
            const int cl = wn + ni * 8 + q2;
            const float v0 = acc[mi][ni][0], v1 = acc[mi][ni][1];
            const float v2 = acc[mi][ni][2], v3 = acc[mi][ni][3];
#pragma unroll
            for (int a = 0; a < 3; ++a) {
                const float w10 = sWf1[a][cl], w11 = sWf1[a][cl + 1];
                const float w20 = sWf2[a][cl], w21 = sWf2[a][cl + 1];
                dA[2 * a]     += v0 * w10 + v1 * w11;
                dA[2 * a + 1] += v0 * w20 + v1 * w21;
                dB[2 * a]     += v2 * w10 + v3 * w11;
                dB[2 * a + 1] += v2 * w20 + v3 * w21;
            }
        }
#pragma unroll
        for (int off = 1; off < 4; off <<= 1)
#pragma unroll
            for (int e = 0; e < 6; ++e) {
                dA[e] += __shfl_xor_sync(0xffffffffu, dA[e], off);
                dB[e] += __shfl_xor_sync(0xffffffffu, dB[e], off);
            }
        if ((lid & 3) == 0) {
            const int rA = wm + mi * 16 + (lid >> 2);
#pragma unroll
            for (int e = 0; e < 6; ++e) {
                sdot[wng][rA][e]     = dA[e];
                sdot[wng][rA + 8][e] = dB[e];
            }
        }
    }
    __syncthreads();

    // finalize colsums (256 cols) and row dots (128 rows), fixed order
    {
        const int c = tid;                 // 0..255
        const int g = c >> 6;
        float cs = sred[2 * g][c & 63] + sred[2 * g + 1][c & 63];
        g_hpart[mtile * 512 + ntile * 256 + c] = cs;
    }
    if (tid < 128) {
        const int r = tid;
        float* dst = g_dotp + ((size_t)(mtile * 128 + r)) * 12 + ntile * 6;
#pragma unroll
        for (int e = 0; e < 6; ++e)
            dst[e] = sdot[0][r][e] + sdot[1][r][e] + sdot[2][r][e] + sdot[3][r][e];
    }
}

// ---------------------------------------------------------------------------
// Kernel 2: S colsum (fixed order) + cterm. <<<1, 512>>>
// ---------------------------------------------------------------------------
__global__ void k_pre(const float* __restrict__ Wf, const float* __restrict__ bf) {
    __shared__ float sS[512];
    const int g = threadIdx.x;
    float s = 0.0f;
    for (int m = 0; m < 512; ++m) s += g_hpart[m * 512 + g];
    sS[g] = s;
    __syncthreads();
    const float inv = 1.0f / (float)(NSTK - 1);
    if (g < 32) {
#pragma unroll
        for (int a = 0; a < NACT; ++a) {
            float p = 0.0f;
            for (int q = g; q < NH; q += 32) p += sS[q] * Wf[a * 1024 + 512 + q];
#pragma unroll
            for (int off = 16; off > 0; off >>= 1)
                p += __shfl_xor_sync(0xffffffffu, p, off);
            if (g == 0) g_cterm[a] = p * inv + bf[a];
        }
    }
}

// ---------------------------------------------------------------------------
// Kernel 3: combine dot partials -> out. 1 thread per stock.
// ---------------------------------------------------------------------------
__global__ void __launch_bounds__(256) k_out2(float* __restrict__ out) {
    __shared__ float sc[3];
    if (threadIdx.x < 3) sc[threadIdx.x] = g_cterm[threadIdx.x];
    __syncthreads();
    const int i = blockIdx.x * 256 + threadIdx.x;
    const float4 d0 = *(const float4*)(g_dotp + (size_t)i * 12);
    const float4 d1 = *(const float4*)(g_dotp + (size_t)i * 12 + 4);
    const float4 d2 = *(const float4*)(g_dotp + (size_t)i * 12 + 8);
    const float inv = 1.0f / (float)(NSTK - 1);
    // slots: [nt0: a0w1,a0w2,a1w1,a1w2,a2w1,a2w2][nt1: same]
    const float p0 = d0.x + d1.z, q0 = d0.y + d1.w;   // a0: w1, w2
    const float p1 = d0.z + d2.x, q1 = d0.w + d2.y;   // a1
    const float p2 = d1.x + d2.z, q2 = d1.y + d2.w;   // a2
    out[(size_t)i * 3 + 0] = fmaxf(p0 - q0 * inv + sc[0], 0.0f);
    out[(size_t)i * 3 + 1] = fmaxf(p1 - q1 * inv + sc[1], 0.0f);
    out[(size_t)i * 3 + 2] = fmaxf(p2 - q2 * inv + sc[2], 0.0f);
}

// ---------------------------------------------------------------------------
// Host launcher
// ---------------------------------------------------------------------------
extern "C" void kernel_launch(void* const* d_in, const int* in_sizes, int n_in,
                              void* d_out, int out_size) {
    const float *x = nullptr, *Wh = nullptr, *bh = nullptr, *Wf = nullptr, *bf = nullptr;
    for (int i = 0; i < n_in; ++i) {
        switch (in_sizes[i]) {
            case NSTK * NFEAT:  x  = (const float*)d_in[i]; break;  // 50331648
            case NH * NFEAT:    Wh = (const float*)d_in[i]; break;  // 393216
            case NH:            bh = (const float*)d_in[i]; break;  // 512
            case NACT * 2 * NH: Wf = (const float*)d_in[i]; break;  // 3072
            case NACT:          bf = (const float*)d_in[i]; break;  // 3
            default: break;
        }
    }
    float* out = (float*)d_out;

    static bool attr_set = false;
    if (!attr_set) {
        cudaFuncSetAttribute(k_gemm, cudaFuncAttributeMaxDynamicSharedMemorySize, SMEM_DYN);
        attr_set = true;
    }

    k_wsplit<<<384, 256>>>(Wh);
    k_gemm<<<dim3(2, 512), 256, SMEM_DYN>>>(x, bh, Wf);
    k_pre<<<1, 512>>>(Wf, bf);
    k_out2<<<NSTK / 256, 256>>>(out);
}

// round 10
// speedup vs baseline: 2.4337x; 2.0849x over previous
#include <cuda_runtime.h>
#include <cuda_fp16.h>
#include <cstdint>
#include <cstddef>

// ---------------------------------------------------------------------------
// Problem constants
// ---------------------------------------------------------------------------
static constexpr int NSTK  = 65536;
static constexpr int NFEAT = 768;
static constexpr int NH    = 512;
static constexpr int NACT  = 3;

// GEMM tiling: CTA 128(M) x 256(N) x 32(K), 256 threads, warp tile 64x64.
// 4-stage cp.async pipeline. x loaded fp32, converted to fp16 in smem.
static constexpr int NKCH = NFEAT / 32;          // 24 K-chunks
// stage: A32 (128x32 f32 = 16KB) + Bh (256x32 f16 = 16KB)
static constexpr int ST_A32 = 0;
static constexpr int ST_BH  = 16384;
static constexpr int STAGE_BYTES = 32768;
static constexpr int STAGES = 4;
static constexpr int A16_OFF  = STAGES * STAGE_BYTES;          // 131072 (8KB)
static constexpr int SMEM_DYN = A16_OFF + 8192;                // 139264

// ---------------------------------------------------------------------------
// Device scratch (static globals: allocation-free)
// ---------------------------------------------------------------------------
__device__ __half g_whh[NH * NFEAT];
__device__ float  g_hpart[512 * 512];              // [m_tile][col] colsum parts
__device__ float  g_dotp[(size_t)NSTK * 12];       // per-row 6 dots x 2 ntiles
__device__ float  g_cterm[NACT];

// ---------------------------------------------------------------------------
// PTX helpers (arch-agnostic, sm_80-level)
// ---------------------------------------------------------------------------
__device__ __forceinline__ uint32_t smem_u32(const void* p) {
    uint32_t a;
    asm("{ .reg .u64 t; cvta.to.shared.u64 t, %1; cvt.u32.u64 %0, t; }" : "=r"(a) : "l"(p));
    return a;
}
__device__ __forceinline__ void cpa16(uint32_t dst, const void* src) {
    asm volatile("cp.async.cg.shared.global [%0], [%1], 16;" :: "r"(dst), "l"(src));
}
__device__ __forceinline__ void cpa_commit() { asm volatile("cp.async.commit_group;"); }
template <int N> __device__ __forceinline__ void cpa_wait() {
    asm volatile("cp.async.wait_group %0;" :: "n"(N));
}
#define LDMX4(r, addr)                                                          \
    asm volatile("ldmatrix.sync.aligned.m8n8.x4.shared.b16 {%0,%1,%2,%3}, [%4];" \
        : "=r"((r)[0]), "=r"((r)[1]), "=r"((r)[2]), "=r"((r)[3]) : "r"(addr))

__device__ __forceinline__ void mma16816(float* d, const uint32_t* a, const uint32_t* b) {
    asm volatile(
        "mma.sync.aligned.m16n8k16.row.col.f32.f16.f16.f32 "
        "{%0,%1,%2,%3}, {%4,%5,%6,%7}, {%8,%9}, {%0,%1,%2,%3};"
        : "+f"(d[0]), "+f"(d[1]), "+f"(d[2]), "+f"(d[3])
        : "r"(a[0]), "r"(a[1]), "r"(a[2]), "r"(a[3]), "r"(b[0]), "r"(b[1]));
}
// 64B-row swizzle for f16 tiles: granule ^= (row>>1)&3
__device__ __forceinline__ uint32_t soff(int row, int g) {
    return (uint32_t)(row * 64 + ((g ^ ((row >> 1) & 3)) << 4));
}

// ---------------------------------------------------------------------------
// Kernel 0: W -> fp16 (tiny)
// ---------------------------------------------------------------------------
__global__ void k_wsplit(const float* __restrict__ wh) {
    int i = blockIdx.x * blockDim.x + threadIdx.x;   // 98304 float4 tasks
    float4 v = ((const float4*)wh)[i];
    ((__half2*)g_whh)[2 * i]     = __halves2half2(__float2half_rn(v.x), __float2half_rn(v.y));
    ((__half2*)g_whh)[2 * i + 1] = __halves2half2(__float2half_rn(v.z), __float2half_rn(v.w));
}

// ---------------------------------------------------------------------------
// Kernel 1: fused GEMM1 + epilogue.
//   h = relu(x @ Wh^T + bh) (fp16 inputs, fp32 accum; h never stored)
//   emits: per-CTA column sums -> g_hpart, per-row layer2 dots -> g_dotp
// grid (2, 512): blockIdx.x = ntile (256 N-cols), blockIdx.y = mtile (128 rows)
// ---------------------------------------------------------------------------
__global__ void __launch_bounds__(256, 1) k_gemm(const float* __restrict__ x,
                                                 const float* __restrict__ bh,
                                                 const float* __restrict__ Wf) {
    extern __shared__ char smem[];
    __shared__ float sbh[256];
    __shared__ float sWf1[3][256];
    __shared__ float sWf2[3][256];
    __shared__ float sred[8][64];
    __shared__ float sdot[4][128][6];
    const uint32_t sb = smem_u32(smem);

    const int tid = threadIdx.x, wid = tid >> 5, lid = tid & 31;
    const int ntile = blockIdx.x, mtile = blockIdx.y;

    sbh[tid] = bh[ntile * 256 + tid];
#pragma unroll
    for (int a = 0; a < 3; ++a) {
        sWf1[a][tid] = Wf[a * 1024 + ntile * 256 + tid];
        sWf2[a][tid] = Wf[a * 1024 + 512 + ntile * 256 + tid];
    }

    const char* pX  = (const char*)x + (size_t)mtile * 128 * 3072;   // f32 rows, 3072B
    const char* pBh = (const char*)g_whh + (size_t)ntile * 256 * 1536;

    auto load_chunk = [&](int k, int s) {
        const uint32_t st = sb + s * STAGE_BYTES;
        // A32: 128 rows x 8 granules (linear 128B rows)
#pragma unroll
        for (int it = 0; it < 4; ++it) {
            int idx = tid + it * 256;
            int r = idx >> 3, g = idx & 7;
            cpa16(st + ST_A32 + r * 128 + g * 16,
                  pX + (size_t)r * 3072 + (size_t)k * 128 + g * 16);
        }
        // B: 256 rows x 4 granules, swizzled 64B rows
#pragma unroll
        for (int it = 0; it < 4; ++it) {
            int idx = tid + it * 256;
            int r = idx >> 2, g = idx & 3;
            cpa16(st + ST_BH + soff(r, g),
                  pBh + (size_t)r * 1536 + (size_t)g * 16 + (size_t)k * 64);
        }
        cpa_commit();
    };

    load_chunk(0, 0);
    load_chunk(1, 1);
    load_chunk(2, 2);

    float acc[4][8][4];
#pragma unroll
    for (int mi = 0; mi < 4; ++mi)
#pragma unroll
        for (int ni = 0; ni < 8; ++ni)
#pragma unroll
            for (int e = 0; e < 4; ++e) acc[mi][ni][e] = 0.0f;

    const int wm = (wid & 1) * 64;        // warp M offset (0, 64)
    const int wn = (wid >> 1) * 64;       // warp N offset (0, 64, 128, 192)
    const int rloc = lid & 15, c0 = lid >> 4;
    const uint32_t aoff0 = soff(wm + rloc, c0);
    const uint32_t boff0 = soff(wn + rloc, c0);

    for (int k = 0; k < NKCH; ++k) {
        cpa_wait<2>();
        __syncthreads();
        if (k + 3 < NKCH) load_chunk(k + 3, (k + 3) & 3);
        else cpa_commit();

        const int sidx = k & 3;
        const uint32_t st = sb + sidx * STAGE_BYTES;

        // ---- convert A32 -> A16 (512 granule tasks of 8 floats each) ----
#pragma unroll
        for (int it = 0; it < 2; ++it) {
            int t = tid + it * 256;
            int r = t >> 2, gh = t & 3;
            const float4* src = (const float4*)(smem + sidx * STAGE_BYTES
                                                + ST_A32 + r * 128 + gh * 32);
            float4 f0 = src[0], f1 = src[1];
            union { __half2 h2v[4]; uint4 u; } th;
            th.h2v[0] = __halves2half2(__float2half_rn(f0.x), __float2half_rn(f0.y));
            th.h2v[1] = __halves2half2(__float2half_rn(f0.z), __float2half_rn(f0.w));
            th.h2v[2] = __halves2half2(__float2half_rn(f1.x), __float2half_rn(f1.y));
            th.h2v[3] = __halves2half2(__float2half_rn(f1.z), __float2half_rn(f1.w));
            *(uint4*)(smem + A16_OFF + soff(r, gh)) = th.u;
        }
        __syncthreads();

        // ---- MMA: 2 K-halves, B in two 32-col halves ----
#pragma unroll
        for (int j = 0; j < 2; ++j) {
            const uint32_t jx = j ? 32u : 0u;
            uint32_t ah[4][4];
#pragma unroll
            for (int mi = 0; mi < 4; ++mi)
                LDMX4(ah[mi], sb + A16_OFF + ((aoff0 + mi * 1024) ^ jx));
#pragma unroll
            for (int half = 0; half < 2; ++half) {
                uint32_t bhf[4][2];
#pragma unroll
                for (int nq = 0; nq < 2; ++nq) {
                    uint32_t t[4];
                    LDMX4(t, st + ST_BH + ((boff0 + (half * 2 + nq) * 1024) ^ jx));
                    bhf[2 * nq][0] = t[0]; bhf[2 * nq][1] = t[2];
                    bhf[2 * nq + 1][0] = t[1]; bhf[2 * nq + 1][1] = t[3];
                }
                const int nb = half * 4;
#pragma unroll
                for (int mi = 0; mi < 4; ++mi)
#pragma unroll
                    for (int ni = 0; ni < 4; ++ni)
                        mma16816(acc[mi][nb + ni], ah[mi], bhf[ni]);
            }
        }
    }
    __syncthreads();

    // ---- Epilogue: bias + relu (in regs), colsums, layer-2 dot partials ----
    const int q2 = (lid & 3) * 2;
#pragma unroll
    for (int mi = 0; mi < 4; ++mi)
#pragma unroll
        for (int ni = 0; ni < 8; ++ni) {
            const int cl = wn + ni * 8 + q2;
            const float b0 = sbh[cl], b1 = sbh[cl + 1];
            acc[mi][ni][0] = fmaxf(acc[mi][ni][0] + b0, 0.0f);
            acc[mi][ni][1] = fmaxf(acc[mi][ni][1] + b1, 0.0f);
            acc[mi][ni][2] = fmaxf(acc[mi][ni][2] + b0, 0.0f);
            acc[mi][ni][3] = fmaxf(acc[mi][ni][3] + b1, 0.0f);
        }

    // column sums over this warp's 64 rows (fixed order)
#pragma unroll
    for (int ni = 0; ni < 8; ++ni) {
        float p0 = 0.0f, p1 = 0.0f;
#pragma unroll
        for (int mi = 0; mi < 4; ++mi) {
            p0 += acc[mi][ni][0] + acc[mi][ni][2];
            p1 += acc[mi][ni][1] + acc[mi][ni][3];
        }
#pragma unroll
        for (int off = 4; off < 32; off <<= 1) {
            p0 += __shfl_xor_sync(0xffffffffu, p0, off);
            p1 += __shfl_xor_sync(0xffffffffu, p1, off);
        }
        if (lid < 4) {
            sred[wid][ni * 8 + 2 * lid]     = p0;
            sred[wid][ni * 8 + 2 * lid + 1] = p1;
        }
    }

    // per-row dot partials with Wf1/Wf2 (6 values per row), per mi block
    const int wng = wid >> 1;
#pragma unroll
    for (int mi = 0; mi < 4; ++mi) {
        float dA[6] = {0, 0, 0, 0, 0, 0}, dB[6] = {0, 0, 0, 0, 0, 0};
#pragma unroll
        for (int ni = 0; ni < 8; ++ni) {
            const int cl = wn + ni * 8 + q2;
            const float v0 = acc[mi][ni][0], v1 = acc[mi][ni][1];
            const float v2 = acc[mi][ni][2], v3 = acc[mi][ni][3];
#pragma unroll
            for (int a = 0; a < 3; ++a) {
                const float w10 = sWf1[a][cl], w11 = sWf1[a][cl + 1];
                const float w20 = sWf2[a][cl], w21 = sWf2[a][cl + 1];
                dA[2 * a]     += v0 * w10 + v1 * w11;
                dA[2 * a + 1] += v0 * w20 + v1 * w21;
                dB[2 * a]     += v2 * w10 + v3 * w11;
                dB[2 * a + 1] += v2 * w20 + v3 * w21;
            }
        }
#pragma unroll
        for (int off = 1; off < 4; off <<= 1)
#pragma unroll
            for (int e = 0; e < 6; ++e) {
                dA[e] += __shfl_xor_sync(0xffffffffu, dA[e], off);
                dB[e] += __shfl_xor_sync(0xffffffffu, dB[e], off);
            }
        if ((lid & 3) == 0) {
            const int rA = wm + mi * 16 + (lid >> 2);
#pragma unroll
            for (int e = 0; e < 6; ++e) {
                sdot[wng][rA][e]     = dA[e];
                sdot[wng][rA + 8][e] = dB[e];
            }
        }
    }
    __syncthreads();

    // finalize colsums (256 cols) and row dots (128 rows), fixed order
    {
        const int c = tid;                 // 0..255
        const int g = c >> 6;
        float cs = sred[2 * g][c & 63] + sred[2 * g + 1][c & 63];
        g_hpart[mtile * 512 + ntile * 256 + c] = cs;
    }
    if (tid < 128) {
        const int r = tid;
        float* dst = g_dotp + ((size_t)(mtile * 128 + r)) * 12 + ntile * 6;
#pragma unroll
        for (int e = 0; e < 6; ++e)
            dst[e] = sdot[0][r][e] + sdot[1][r][e] + sdot[2][r][e] + sdot[3][r][e];
    }
}

// ---------------------------------------------------------------------------
// Kernel 2: S colsum (fixed order) + cterm. <<<1, 512>>>
// ---------------------------------------------------------------------------
__global__ void k_pre(const float* __restrict__ Wf, const float* __restrict__ bf) {
    __shared__ float sS[512];
    const int g = threadIdx.x;
    float s = 0.0f;
    for (int m = 0; m < 512; ++m) s += g_hpart[m * 512 + g];
    sS[g] = s;
    __syncthreads();
    const float inv = 1.0f / (float)(NSTK - 1);
    if (g < 32) {
#pragma unroll
        for (int a = 0; a < NACT; ++a) {
            float p = 0.0f;
            for (int q = g; q < NH; q += 32) p += sS[q] * Wf[a * 1024 + 512 + q];
#pragma unroll
            for (int off = 16; off > 0; off >>= 1)
                p += __shfl_xor_sync(0xffffffffu, p, off);
            if (g == 0) g_cterm[a] = p * inv + bf[a];
        }
    }
}

// ---------------------------------------------------------------------------
// Kernel 3: combine dot partials -> out. 1 thread per stock.
// ---------------------------------------------------------------------------
__global__ void __launch_bounds__(256) k_out2(float* __restrict__ out) {
    __shared__ float sc[3];
    if (threadIdx.x < 3) sc[threadIdx.x] = g_cterm[threadIdx.x];
    __syncthreads();
    const int i = blockIdx.x * 256 + threadIdx.x;
    const float4 d0 = *(const float4*)(g_dotp + (size_t)i * 12);
    const float4 d1 = *(const float4*)(g_dotp + (size_t)i * 12 + 4);
    const float4 d2 = *(const float4*)(g_dotp + (size_t)i * 12 + 8);
    const float inv = 1.0f / (float)(NSTK - 1);
    // slots: [nt0: a0w1,a0w2,a1w1,a1w2,a2w1,a2w2][nt1: same]
    const float p0 = d0.x + d1.z, q0 = d0.y + d1.w;   // a0: w1, w2
    const float p1 = d0.z + d2.x, q1 = d0.w + d2.y;   // a1
    const float p2 = d1.x + d2.z, q2 = d1.y + d2.w;   // a2
    out[(size_t)i * 3 + 0] = fmaxf(p0 - q0 * inv + sc[0], 0.0f);
    out[(size_t)i * 3 + 1] = fmaxf(p1 - q1 * inv + sc[1], 0.0f);
    out[(size_t)i * 3 + 2] = fmaxf(p2 - q2 * inv + sc[2], 0.0f);
}

// ---------------------------------------------------------------------------
// Host launcher
// ---------------------------------------------------------------------------
extern "C" void kernel_launch(void* const* d_in, const int* in_sizes, int n_in,
                              void* d_out, int out_size) {
    const float *x = nullptr, *Wh = nullptr, *bh = nullptr, *Wf = nullptr, *bf = nullptr;
    for (int i = 0; i < n_in; ++i) {
        switch (in_sizes[i]) {
            case NSTK * NFEAT:  x  = (const float*)d_in[i]; break;  // 50331648
            case NH * NFEAT:    Wh = (const float*)d_in[i]; break;  // 393216
            case NH:            bh = (const float*)d_in[i]; break;  // 512
            case NACT * 2 * NH: Wf = (const float*)d_in[i]; break;  // 3072
            case NACT:          bf = (const float*)d_in[i]; break;  // 3
            default: break;
        }
    }
    float* out = (float*)d_out;

    static bool attr_set = false;
    if (!attr_set) {
        cudaFuncSetAttribute(k_gemm, cudaFuncAttributeMaxDynamicSharedMemorySize, SMEM_DYN);
        attr_set = true;
    }

    k_wsplit<<<384, 256>>>(Wh);
    k_gemm<<<dim3(2, 512), 256, SMEM_DYN>>>(x, bh, Wf);
    k_pre<<<1, 512>>>(Wf, bf);
    k_out2<<<NSTK / 256, 256>>>(out);
}

// round 11
// speedup vs baseline: 2.7735x; 1.1397x over previous
#include <cuda_runtime.h>
#include <cuda_fp16.h>
#include <cstdint>
#include <cstddef>

// ---------------------------------------------------------------------------
// Problem constants
// ---------------------------------------------------------------------------
static constexpr int NSTK  = 65536;
static constexpr int NFEAT = 768;
static constexpr int NH    = 512;
static constexpr int NACT  = 3;

// GEMM tiling: CTA 128(M) x 256(N) x 32(K), 256 threads, warp tile 64x64.
// B: 4-stage cp.async (16KB/stage). A: LDG->regs->convert->STS, double-buffered
// fp16 tile (2 x 8KB).
static constexpr int NKCH = NFEAT / 32;          // 24 K-chunks
static constexpr int STAGE_BYTES = 16384;        // B only: 256x32 f16
static constexpr int STAGES = 4;
static constexpr int A16_OFF  = STAGES * STAGE_BYTES;          // 65536
static constexpr int SMEM_DYN = A16_OFF + 2 * 8192;            // 81920

// ---------------------------------------------------------------------------
// Device scratch (static globals: allocation-free)
// ---------------------------------------------------------------------------
__device__ __half g_whh[NH * NFEAT];
__device__ float  g_hpart[512 * 512];              // [m_tile][col] colsum parts
__device__ float  g_dotp[(size_t)NSTK * 12];       // per-row 6 dots x 2 ntiles
__device__ float  g_cterm[NACT];

// ---------------------------------------------------------------------------
// PTX helpers (arch-agnostic, sm_80-level)
// ---------------------------------------------------------------------------
__device__ __forceinline__ uint32_t smem_u32(const void* p) {
    uint32_t a;
    asm("{ .reg .u64 t; cvta.to.shared.u64 t, %1; cvt.u32.u64 %0, t; }" : "=r"(a) : "l"(p));
    return a;
}
__device__ __forceinline__ void cpa16(uint32_t dst, const void* src) {
    asm volatile("cp.async.cg.shared.global [%0], [%1], 16;" :: "r"(dst), "l"(src));
}
__device__ __forceinline__ void cpa_commit() { asm volatile("cp.async.commit_group;"); }
template <int N> __device__ __forceinline__ void cpa_wait() {
    asm volatile("cp.async.wait_group %0;" :: "n"(N));
}
#define LDMX4(r, addr)                                                          \
    asm volatile("ldmatrix.sync.aligned.m8n8.x4.shared.b16 {%0,%1,%2,%3}, [%4];" \
        : "=r"((r)[0]), "=r"((r)[1]), "=r"((r)[2]), "=r"((r)[3]) : "r"(addr))

__device__ __forceinline__ void mma16816(float* d, const uint32_t* a, const uint32_t* b) {
    asm volatile(
        "mma.sync.aligned.m16n8k16.row.col.f32.f16.f16.f32 "
        "{%0,%1,%2,%3}, {%4,%5,%6,%7}, {%8,%9}, {%0,%1,%2,%3};"
        : "+f"(d[0]), "+f"(d[1]), "+f"(d[2]), "+f"(d[3])
        : "r"(a[0]), "r"(a[1]), "r"(a[2]), "r"(a[3]), "r"(b[0]), "r"(b[1]));
}
// 64B-row swizzle for f16 tiles: granule ^= (row>>1)&3
__device__ __forceinline__ uint32_t soff(int row, int g) {
    return (uint32_t)(row * 64 + ((g ^ ((row >> 1) & 3)) << 4));
}

// ---------------------------------------------------------------------------
// Kernel 0: W -> fp16 (tiny)
// ---------------------------------------------------------------------------
__global__ void k_wsplit(const float* __restrict__ wh) {
    int i = blockIdx.x * blockDim.x + threadIdx.x;   // 98304 float4 tasks
    float4 v = ((const float4*)wh)[i];
    ((__half2*)g_whh)[2 * i]     = __halves2half2(__float2half_rn(v.x), __float2half_rn(v.y));
    ((__half2*)g_whh)[2 * i + 1] = __halves2half2(__float2half_rn(v.z), __float2half_rn(v.w));
}

// ---------------------------------------------------------------------------
// Kernel 1: fused GEMM1 + epilogue.
//   h = relu(x @ Wh^T + bh) (fp16 in, fp32 accum; h never stored)
//   emits: per-CTA column sums -> g_hpart, per-row layer2 dots -> g_dotp
// grid (2, 512): blockIdx.x = ntile (256 N-cols), blockIdx.y = mtile (128 rows)
// ---------------------------------------------------------------------------
__global__ void __launch_bounds__(256, 1) k_gemm(const float* __restrict__ x,
                                                 const float* __restrict__ bh,
                                                 const float* __restrict__ Wf) {
    extern __shared__ char smem[];
    __shared__ float sbh[256];
    __shared__ float sWf1[3][256];
    __shared__ float sWf2[3][256];
    __shared__ float sred[8][64];
    __shared__ float sdot[4][128][6];
    const uint32_t sb = smem_u32(smem);

    const int tid = threadIdx.x, wid = tid >> 5, lid = tid & 31;
    const int ntile = blockIdx.x, mtile = blockIdx.y;

    sbh[tid] = bh[ntile * 256 + tid];
#pragma unroll
    for (int a = 0; a < 3; ++a) {
        sWf1[a][tid] = Wf[a * 1024 + ntile * 256 + tid];
        sWf2[a][tid] = Wf[a * 1024 + 512 + ntile * 256 + tid];
    }

    const char* pBh = (const char*)g_whh + (size_t)ntile * 256 * 1536;

    auto load_B = [&](int k, int s) {
        const uint32_t st = sb + s * STAGE_BYTES;
#pragma unroll
        for (int it = 0; it < 4; ++it) {
            int idx = tid + it * 256;
            int r = idx >> 2, g = idx & 3;
            cpa16(st + soff(r, g),
                  pBh + (size_t)r * 1536 + (size_t)g * 16 + (size_t)k * 64);
        }
        cpa_commit();
    };

    load_B(0, 0);
    load_B(1, 1);
    load_B(2, 2);

    // A fetch mapping: thread t covers row = t>>1 (of 128), col-half = t&1
    // (16 f32 = 64B), i.e. granules {2*half, 2*half+1} of the 64B fp16 row.
    const int arow = tid >> 1, ahalf = tid & 1;
    const char* pXme = (const char*)x + (size_t)(mtile * 128 + arow) * 3072 + ahalf * 64;
    const uint32_t aw0 = soff(arow, 2 * ahalf);
    const uint32_t aw1 = soff(arow, 2 * ahalf + 1);

    float4 pf0, pf1, pf2, pf3;
    {
        const float4* s0 = (const float4*)(pXme);
        pf0 = s0[0]; pf1 = s0[1]; pf2 = s0[2]; pf3 = s0[3];
    }

    float acc[4][8][4];
#pragma unroll
    for (int mi = 0; mi < 4; ++mi)
#pragma unroll
        for (int ni = 0; ni < 8; ++ni)
#pragma unroll
            for (int e = 0; e < 4; ++e) acc[mi][ni][e] = 0.0f;

    const int wm = (wid & 1) * 64;        // warp M offset (0, 64)
    const int wn = (wid >> 1) * 64;       // warp N offset (0, 64, 128, 192)
    const int rloc = lid & 15, c0 = lid >> 4;
    const uint32_t aoff0 = soff(wm + rloc, c0);
    const uint32_t boff0 = soff(wn + rloc, c0);

    for (int k = 0; k < NKCH; ++k) {
        // convert prefetched A regs -> fp16, STS to double buffer
        const uint32_t abuf = sb + A16_OFF + (k & 1) * 8192;
        {
            union { __half2 h[4]; uint4 u; } t0, t1;
            t0.h[0] = __halves2half2(__float2half_rn(pf0.x), __float2half_rn(pf0.y));
            t0.h[1] = __halves2half2(__float2half_rn(pf0.z), __float2half_rn(pf0.w));
            t0.h[2] = __halves2half2(__float2half_rn(pf1.x), __float2half_rn(pf1.y));
            t0.h[3] = __halves2half2(__float2half_rn(pf1.z), __float2half_rn(pf1.w));
            t1.h[0] = __halves2half2(__float2half_rn(pf2.x), __float2half_rn(pf2.y));
            t1.h[1] = __halves2half2(__float2half_rn(pf2.z), __float2half_rn(pf2.w));
            t1.h[2] = __halves2half2(__float2half_rn(pf3.x), __float2half_rn(pf3.y));
            t1.h[3] = __halves2half2(__float2half_rn(pf3.z), __float2half_rn(pf3.w));
            *(uint4*)(smem + (abuf - sb) + aw0) = t0.u;
            *(uint4*)(smem + (abuf - sb) + aw1) = t1.u;
        }
        // prefetch next A chunk (clamped; latency hidden under MMA phase)
        {
            const int kn = (k + 1 < NKCH) ? k + 1 : k;
            const float4* s0 = (const float4*)(pXme + (size_t)kn * 128);
            pf0 = s0[0]; pf1 = s0[1]; pf2 = s0[2]; pf3 = s0[3];
        }

        cpa_wait<2>();
        __syncthreads();
        if (k + 3 < NKCH) load_B(k + 3, (k + 3) & 3);
        else cpa_commit();

        const uint32_t st = sb + (k & 3) * STAGE_BYTES;

        // ---- MMA: 2 K16-halves; 8 ldmatrix.x4 then 32 MMAs per half ----
#pragma unroll
        for (int j = 0; j < 2; ++j) {
            const uint32_t jx = j ? 32u : 0u;
            uint32_t ah[4][4];
#pragma unroll
            for (int mi = 0; mi < 4; ++mi)
                LDMX4(ah[mi], abuf + ((aoff0 + mi * 1024) ^ jx));
            uint32_t bfr[8][2];
#pragma unroll
            for (int nq = 0; nq < 4; ++nq) {
                uint32_t t[4];
                LDMX4(t, st + ((boff0 + nq * 1024) ^ jx));
                bfr[2 * nq][0] = t[0]; bfr[2 * nq][1] = t[2];
                bfr[2 * nq + 1][0] = t[1]; bfr[2 * nq + 1][1] = t[3];
            }
#pragma unroll
            for (int mi = 0; mi < 4; ++mi)
#pragma unroll
                for (int ni = 0; ni < 8; ++ni)
                    mma16816(acc[mi][ni], ah[mi], bfr[ni]);
        }
    }
    __syncthreads();

    // ---- Epilogue: bias + relu (in regs), colsums, layer-2 dot partials ----
    const int q2 = (lid & 3) * 2;
#pragma unroll
    for (int mi = 0; mi < 4; ++mi)
#pragma unroll
        for (int ni = 0; ni < 8; ++ni) {
            const int cl = wn + ni * 8 + q2;
            const float b0 = sbh[cl], b1 = sbh[cl + 1];
            acc[mi][ni][0] = fmaxf(acc[mi][ni][0] + b0, 0.0f);
            acc[mi][ni][1] = fmaxf(acc[mi][ni][1] + b1, 0.0f);
            acc[mi][ni][2] = fmaxf(acc[mi][ni][2] + b0, 0.0f);
            acc[mi][ni][3] = fmaxf(acc[mi][ni][3] + b1, 0.0f);
        }

    // column sums over this warp's 64 rows (fixed order)
#pragma unroll
    for (int ni = 0; ni < 8; ++ni) {
        float p0 = 0.0f, p1 = 0.0f;
#pragma unroll
        for (int mi = 0; mi < 4; ++mi) {
            p0 += acc[mi][ni][0] + acc[mi][ni][2];
            p1 += acc[mi][ni][1] + acc[mi][ni][3];
        }
#pragma unroll
        for (int off = 4; off < 32; off <<= 1) {
            p0 += __shfl_xor_sync(0xffffffffu, p0, off);
            p1 += __shfl_xor_sync(0xffffffffu, p1, off);
        }
        if (lid < 4) {
            sred[wid][ni * 8 + 2 * lid]     = p0;
            sred[wid][ni * 8 + 2 * lid + 1] = p1;
        }
    }

    // per-row dot partials with Wf1/Wf2 (6 values per row), per mi block
    const int wng = wid >> 1;
#pragma unroll
    for (int mi = 0; mi < 4; ++mi) {
        float dA[6] = {0, 0, 0, 0, 0, 0}, dB[6] = {0, 0, 0, 0, 0, 0};
#pragma unroll
        for (int ni = 0; ni < 8; ++ni) {
            const int cl = wn + ni * 8 + q2;
            const float v0 = acc[mi][ni][0], v1 = acc[mi][ni][1];
            const float v2 = acc[mi][ni][2], v3 = acc[mi][ni][3];
#pragma unroll
            for (int a = 0; a < 3; ++a) {
                const float w10 = sWf1[a][cl], w11 = sWf1[a][cl + 1];
                const float w20 = sWf2[a][cl], w21 = sWf2[a][cl + 1];
                dA[2 * a]     += v0 * w10 + v1 * w11;
                dA[2 * a + 1] += v0 * w20 + v1 * w21;
                dB[2 * a]     += v2 * w10 + v3 * w11;
                dB[2 * a + 1] += v2 * w20 + v3 * w21;
            }
        }
#pragma unroll
        for (int off = 1; off < 4; off <<= 1)
#pragma unroll
            for (int e = 0; e < 6; ++e) {
                dA[e] += __shfl_xor_sync(0xffffffffu, dA[e], off);
                dB[e] += __shfl_xor_sync(0xffffffffu, dB[e], off);
            }
        if ((lid & 3) == 0) {
            const int rA = wm + mi * 16 + (lid >> 2);
#pragma unroll
            for (int e = 0; e < 6; ++e) {
                sdot[wng][rA][e]     = dA[e];
                sdot[wng][rA + 8][e] = dB[e];
            }
        }
    }
    __syncthreads();

    // finalize colsums (256 cols) and row dots (128 rows), fixed order
    {
        const int c = tid;                 // 0..255
        const int g = c >> 6;
        float cs = sred[2 * g][c & 63] + sred[2 * g + 1][c & 63];
        g_hpart[mtile * 512 + ntile * 256 + c] = cs;
    }
    if (tid < 128) {
        const int r = tid;
        float* dst = g_dotp + ((size_t)(mtile * 128 + r)) * 12 + ntile * 6;
#pragma unroll
        for (int e = 0; e < 6; ++e)
            dst[e] = sdot[0][r][e] + sdot[1][r][e] + sdot[2][r][e] + sdot[3][r][e];
    }
}

// ---------------------------------------------------------------------------
// Kernel 2: S colsum (fixed order) + cterm. <<<1, 512>>>
// ---------------------------------------------------------------------------
__global__ void k_pre(const float* __restrict__ Wf, const float* __restrict__ bf) {
    __shared__ float sS[512];
    const int g = threadIdx.x;
    float s = 0.0f;
    for (int m = 0; m < 512; ++m) s += g_hpart[m * 512 + g];
    sS[g] = s;
    __syncthreads();
    const float inv = 1.0f / (float)(NSTK - 1);
    if (g < 32) {
#pragma unroll
        for (int a = 0; a < NACT; ++a) {
            float p = 0.0f;
            for (int q = g; q < NH; q += 32) p += sS[q] * Wf[a * 1024 + 512 + q];
#pragma unroll
            for (int off = 16; off > 0; off >>= 1)
                p += __shfl_xor_sync(0xffffffffu, p, off);
            if (g == 0) g_cterm[a] = p * inv + bf[a];
        }
    }
}

// ---------------------------------------------------------------------------
// Kernel 3: combine dot partials -> out. 1 thread per stock.
// ---------------------------------------------------------------------------
__global__ void __launch_bounds__(256) k_out2(float* __restrict__ out) {
    __shared__ float sc[3];
    if (threadIdx.x < 3) sc[threadIdx.x] = g_cterm[threadIdx.x];
    __syncthreads();
    const int i = blockIdx.x * 256 + threadIdx.x;
    const float4 d0 = *(const float4*)(g_dotp + (size_t)i * 12);
    const float4 d1 = *(const float4*)(g_dotp + (size_t)i * 12 + 4);
    const float4 d2 = *(const float4*)(g_dotp + (size_t)i * 12 + 8);
    const float inv = 1.0f / (float)(NSTK - 1);
    // slots: [nt0: a0w1,a0w2,a1w1,a1w2,a2w1,a2w2][nt1: same]
    const float p0 = d0.x + d1.z, q0 = d0.y + d1.w;   // a0: w1, w2
    const float p1 = d0.z + d2.x, q1 = d0.w + d2.y;   // a1
    const float p2 = d1.x + d2.z, q2 = d1.y + d2.w;   // a2
    out[(size_t)i * 3 + 0] = fmaxf(p0 - q0 * inv + sc[0], 0.0f);
    out[(size_t)i * 3 + 1] = fmaxf(p1 - q1 * inv + sc[1], 0.0f);
    out[(size_t)i * 3 + 2] = fmaxf(p2 - q2 * inv + sc[2], 0.0f);
}

// ---------------------------------------------------------------------------
// Host launcher
// ---------------------------------------------------------------------------
extern "C" void kernel_launch(void* const* d_in, const int* in_sizes, int n_in,
                              void* d_out, int out_size) {
    const float *x = nullptr, *Wh = nullptr, *bh = nullptr, *Wf = nullptr, *bf = nullptr;
    for (int i = 0; i < n_in; ++i) {
        switch (in_sizes[i]) {
            case NSTK * NFEAT:  x  = (const float*)d_in[i]; break;  // 50331648
            case NH * NFEAT:    Wh = (const float*)d_in[i]; break;  // 393216
            case NH:            bh = (const float*)d_in[i]; break;  // 512
            case NACT * 2 * NH: Wf = (const float*)d_in[i]; break;  // 3072
            case NACT:          bf = (const float*)d_in[i]; break;  // 3
            default: break;
        }
    }
    float* out = (float*)d_out;

    static bool attr_set = false;
    if (!attr_set) {
        cudaFuncSetAttribute(k_gemm, cudaFuncAttributeMaxDynamicSharedMemorySize, SMEM_DYN);
        attr_set = true;
    }

    k_wsplit<<<384, 256>>>(Wh);
    k_gemm<<<dim3(2, 512), 256, SMEM_DYN>>>(x, bh, Wf);
    k_pre<<<1, 512>>>(Wf, bf);
    k_out2<<<NSTK / 256, 256>>>(out);
}